// round 1
// baseline (speedup 1.0000x reference)
#include <cuda_runtime.h>
#include <math.h>

#define NN 4096
#define FF 128
#define HEADS 8
#define UU 8
#define MCOLS 80     // 72 data cols (8 heads x (8 V + 1 exp_er)) + deg col(72) + pad to 80
#define KCH 4        // K-split for the big matmul
#define BM 64
#define BK 32

// Scratch (no allocations allowed -> __device__ globals)
__device__ float g_M[NN * MCOLS];            // [N, 80] : V columns, exp(e_r) columns, ones col
__device__ float g_EL[HEADS * NN];           // e_l[h, j]
__device__ float g_Ypart[KCH][NN * MCOLS];   // partial A @ M per K-chunk

// ---------------------------------------------------------------------------
// Kernel 1: per node j compute HW[h,j,u], e_l, e_r, build M row and EL.
// grid = N blocks, 64 threads (thread t -> head h=t/8, unit u=t%8)
// ---------------------------------------------------------------------------
__global__ void prep_kernel(const float* __restrict__ H,
                            const float* __restrict__ W,
                            const float* __restrict__ al,
                            const float* __restrict__ ar) {
    int j = blockIdx.x;
    int t = threadIdx.x;
    int h = t >> 3, u = t & 7;

    __shared__ float sH[FF];
    sH[t]      = H[j * FF + t];
    sH[t + 64] = H[j * FF + t + 64];
    __syncthreads();

    // hw = dot(H[j,:], W[h,:,u])
    float acc = 0.f;
    const float* Wp = W + h * FF * UU + u;
#pragma unroll 8
    for (int f = 0; f < FF; f++) acc += sH[f] * Wp[f * UU];

    // reduce over u within each 8-lane group (xor-reduce -> all lanes get sum)
    float el = acc * al[h * UU + u];
    float er = acc * ar[h * UU + u];
#pragma unroll
    for (int m = 4; m; m >>= 1) {
        el += __shfl_xor_sync(0xffffffffu, el, m);
        er += __shfl_xor_sync(0xffffffffu, er, m);
    }

    float eer = expf(er);
    float* Mrow = g_M + (size_t)j * MCOLS;
    Mrow[h * 9 + u] = eer * acc;            // V[h,j,u]
    if (u == 0) {
        Mrow[h * 9 + 8] = eer;              // exp(e_r[h,j]) column (for denom sum)
        g_EL[h * NN + j] = el;
    }
    if (t == 0) {
        Mrow[72] = 1.0f;                    // ones column -> deg(i)
#pragma unroll
        for (int c = 73; c < MCOLS; c++) Mrow[c] = 0.f;
    }
}

// ---------------------------------------------------------------------------
// Kernel 2: Ypart[kc] = A[:, kchunk] @ M[kchunk, :]
// grid = (N/BM, KCH), 256 threads. Per-thread 4x5 microtile.
// ---------------------------------------------------------------------------
__global__ void __launch_bounds__(256) spmm_kernel(const float* __restrict__ A) {
    __shared__ float sA[BM][BK + 1];     // [row][k], pad for conflict-free
    __shared__ float sM[BK][MCOLS];      // [k][col]

    int rowBlock = blockIdx.x;
    int kc = blockIdx.y;
    int row0 = rowBlock * BM;
    int k0 = kc * (NN / KCH);

    int tid = threadIdx.x;
    int tx = tid & 15;        // col group (5 cols)
    int ty = tid >> 4;        // row group (4 rows)

    float acc[4][5];
#pragma unroll
    for (int r = 0; r < 4; r++)
#pragma unroll
        for (int c = 0; c < 5; c++) acc[r][c] = 0.f;

    // hoisted load coordinates
    int mr[10], mc[10];
#pragma unroll
    for (int i = 0; i < 10; i++) {
        int lin = tid + i * 256;
        mr[i] = lin / MCOLS;
        mc[i] = lin % MCOLS;
    }

    for (int kt = 0; kt < NN / KCH; kt += BK) {
        // A tile: each warp writes one row per i, k = lane -> coalesced 128B
#pragma unroll
        for (int i = 0; i < 8; i++) {
            int lin = tid + i * 256;
            int r = lin >> 5, k = lin & 31;
            sA[r][k] = A[(size_t)(row0 + r) * NN + (k0 + kt + k)];
        }
        // M tile
#pragma unroll
        for (int i = 0; i < 10; i++) {
            sM[mr[i]][mc[i]] = g_M[(size_t)(k0 + kt + mr[i]) * MCOLS + mc[i]];
        }
        __syncthreads();

#pragma unroll
        for (int kk = 0; kk < BK; kk++) {
            float a0 = sA[ty * 4 + 0][kk];
            float a1 = sA[ty * 4 + 1][kk];
            float a2 = sA[ty * 4 + 2][kk];
            float a3 = sA[ty * 4 + 3][kk];
            float b[5];
#pragma unroll
            for (int c = 0; c < 5; c++) b[c] = sM[kk][tx * 5 + c];
#pragma unroll
            for (int c = 0; c < 5; c++) {
                acc[0][c] += a0 * b[c];
                acc[1][c] += a1 * b[c];
                acc[2][c] += a2 * b[c];
                acc[3][c] += a3 * b[c];
            }
        }
        __syncthreads();
    }

#pragma unroll
    for (int r = 0; r < 4; r++)
#pragma unroll
        for (int c = 0; c < 5; c++)
            g_Ypart[kc][(size_t)(row0 + ty * 4 + r) * MCOLS + tx * 5 + c] = acc[r][c];
}

// ---------------------------------------------------------------------------
// Kernel 3: combine partials, compute denom, elu, write output [N, 64]
// grid = N blocks, 64 threads (h,u)
// ---------------------------------------------------------------------------
__global__ void finalize_kernel(float* __restrict__ out) {
    int i = blockIdx.x;
    int t = threadIdx.x;
    int h = t >> 3, u = t & 7;

    float y = 0.f, s = 0.f, deg = 0.f;
#pragma unroll
    for (int p = 0; p < KCH; p++) {
        const float* Yp = g_Ypart[p] + (size_t)i * MCOLS;
        y   += Yp[h * 9 + u];
        s   += Yp[h * 9 + 8];
        deg += Yp[72];
    }
    float eel = expf(g_EL[h * NN + i]);
    float denom = ((float)NN - deg) + eel * s;
    float v = eel * y / denom;
    out[i * 64 + h * 8 + u] = (v > 0.f) ? v : expm1f(v);
}

// ---------------------------------------------------------------------------
extern "C" void kernel_launch(void* const* d_in, const int* in_sizes, int n_in,
                              void* d_out, int out_size) {
    const float* A  = (const float*)d_in[0];
    const float* H  = (const float*)d_in[1];
    const float* W  = (const float*)d_in[2];
    const float* al = (const float*)d_in[3];
    const float* ar = (const float*)d_in[4];
    float* out = (float*)d_out;

    prep_kernel<<<NN, 64>>>(H, W, al, ar);
    dim3 grid(NN / BM, KCH);
    spmm_kernel<<<grid, 256>>>(A);
    finalize_kernel<<<NN, 64>>>(out);
}

// round 3
// speedup vs baseline: 1.3068x; 1.3068x over previous
#include <cuda_runtime.h>
#include <math.h>

#define NN 4096
#define FF 128
#define MCOLS 80      // 72 data cols (8 heads x (8 V + exp_er)) + deg col(72) + pad
#define KCH 8         // K-split of the big matmul (256 CTAs)
#define BM 128
#define BK 32
#define SA_STRIDE 132 // padded row stride of transposed A tile (floats)

// Scratch (no allocations allowed -> __device__ globals)
__device__ float g_M[NN * MCOLS];
__device__ float g_EL[8 * NN];
__device__ float g_Ypart[KCH][NN * MCOLS];

typedef unsigned long long ull;

__device__ __forceinline__ ull pack2(float lo, float hi) {
    ull r; asm("mov.b64 %0, {%1, %2};" : "=l"(r) : "f"(lo), "f"(hi)); return r;
}
__device__ __forceinline__ void fma2(ull& d, ull a, ull b) {
    asm("fma.rn.f32x2 %0, %1, %2, %3;" : "=l"(d) : "l"(a), "l"(b), "l"(d));
}

// ---------------------------------------------------------------------------
// Kernel 1: build M rows + EL. Block = 256 threads, handles 32 nodes.
// W staged in smem as sW[f][h*8+u] -> lanes (consecutive hu) hit consecutive
// banks: conflict-free. H rows broadcast via lds.128.
// ---------------------------------------------------------------------------
__global__ void __launch_bounds__(256) prep_kernel(const float* __restrict__ H,
                                                   const float* __restrict__ W,
                                                   const float* __restrict__ al,
                                                   const float* __restrict__ ar) {
    __shared__ __align__(16) float sW[FF * 64];   // 32 KB : [f][hu]
    __shared__ __align__(16) float sH[32 * FF];   // 16 KB : [j_local][f]
    int tid = threadIdx.x;
    int j0 = blockIdx.x * 32;

#pragma unroll
    for (int i = 0; i < 32; i++) {             // stage W: coalesced read, scatter
        int lin = tid + i * 256;               // lin = h*1024 + f*8 + u
        int h = lin >> 10, f = (lin >> 3) & 127, u = lin & 7;
        sW[f * 64 + h * 8 + u] = W[lin];
    }
#pragma unroll
    for (int i = 0; i < 16; i++) {             // stage 32 H rows (same layout)
        int lin = tid + i * 256;
        sH[lin] = H[(size_t)j0 * FF + lin];
    }
    __syncthreads();

    int hu = tid & 63;
    int jj = tid >> 6;                          // 0..3
    int h = hu >> 3, u = hu & 7;
    float alv = al[hu];
    float arv = ar[hu];

    for (int jg = 0; jg < 8; jg++) {
        int jl = jj + 4 * jg;                   // 0..31
        const float* hp = sH + jl * FF;
        float acc = 0.f;
#pragma unroll
        for (int f = 0; f < FF; f += 4) {
            float4 hv = *(const float4*)(hp + f);
            acc += hv.x * sW[(f + 0) * 64 + hu];
            acc += hv.y * sW[(f + 1) * 64 + hu];
            acc += hv.z * sW[(f + 2) * 64 + hu];
            acc += hv.w * sW[(f + 3) * 64 + hu];
        }
        float el = acc * alv, er = acc * arv;
#pragma unroll
        for (int m = 4; m; m >>= 1) {           // reduce over u (8-lane groups)
            el += __shfl_xor_sync(0xffffffffu, el, m);
            er += __shfl_xor_sync(0xffffffffu, er, m);
        }
        float eer = expf(er);
        int j = j0 + jl;
        float* Mrow = g_M + (size_t)j * MCOLS;
        Mrow[h * 9 + u] = eer * acc;            // V[h,j,u]
        if (u == 0) {
            Mrow[h * 9 + 8] = eer;              // exp(e_r) column
            g_EL[h * NN + j] = el;
        }
        if (hu == 0) {
            Mrow[72] = 1.0f;                    // ones -> deg
#pragma unroll
            for (int c = 73; c < MCOLS; c++) Mrow[c] = 0.f;
        }
    }
}

// ---------------------------------------------------------------------------
// Kernel 2: Ypart[kc] = A[:, kchunk] @ M[kchunk, :]
// 256 threads, microtile 4 rows x 10 cols via fma.rn.f32x2 (20 FMA2/kk).
// ---------------------------------------------------------------------------
__global__ void __launch_bounds__(256) spmm_kernel(const float* __restrict__ A) {
    __shared__ __align__(16) float sAT[BK * SA_STRIDE]; // [k][m], padded
    __shared__ __align__(16) float sM[BK * MCOLS];      // [k][c]

    int tid = threadIdx.x;
    int row0 = blockIdx.x * BM;
    int k0 = blockIdx.y * (NN / KCH);

    int cg = tid & 7;       // col group: 10 cols
    int rg = tid >> 3;      // row group: 4 rows (0..31)

    ull acc[4][5];
#pragma unroll
    for (int r = 0; r < 4; r++)
#pragma unroll
        for (int p = 0; p < 5; p++) acc[r][p] = 0ull;

    int kq = tid & 7;       // k-quad for A loads
    int rr = tid >> 3;      // base row for A loads

    for (int kt = 0; kt < NN / KCH; kt += BK) {
        // A tile: float4 along k (coalesced), transpose-scatter to sAT[k][row]
#pragma unroll
        for (int i = 0; i < 4; i++) {
            int row = rr + 32 * i;
            float4 v = *(const float4*)(A + (size_t)(row0 + row) * NN + (k0 + kt + kq * 4));
            sAT[(kq * 4 + 0) * SA_STRIDE + row] = v.x;
            sAT[(kq * 4 + 1) * SA_STRIDE + row] = v.y;
            sAT[(kq * 4 + 2) * SA_STRIDE + row] = v.z;
            sAT[(kq * 4 + 3) * SA_STRIDE + row] = v.w;
        }
        // M tile: layout identical to global, straight coalesced copy
#pragma unroll
        for (int i = 0; i < 10; i++) {
            int lin = tid + i * 256;
            sM[lin] = g_M[(size_t)(k0 + kt) * MCOLS + lin];
        }
        __syncthreads();

#pragma unroll
        for (int kk = 0; kk < BK; kk++) {
            const float* ap = sAT + kk * SA_STRIDE + rg * 4;
            float4 a4 = *(const float4*)ap;                  // 4 row values
            ull a0 = pack2(a4.x, a4.x);
            ull a1 = pack2(a4.y, a4.y);
            ull a2 = pack2(a4.z, a4.z);
            ull a3 = pack2(a4.w, a4.w);
            const float* mp = sM + kk * MCOLS + cg * 10;
            ull b0 = *(const ull*)(mp + 0);
            ull b1 = *(const ull*)(mp + 2);
            ull b2 = *(const ull*)(mp + 4);
            ull b3 = *(const ull*)(mp + 6);
            ull b4 = *(const ull*)(mp + 8);
            fma2(acc[0][0], a0, b0); fma2(acc[0][1], a0, b1); fma2(acc[0][2], a0, b2);
            fma2(acc[0][3], a0, b3); fma2(acc[0][4], a0, b4);
            fma2(acc[1][0], a1, b0); fma2(acc[1][1], a1, b1); fma2(acc[1][2], a1, b2);
            fma2(acc[1][3], a1, b3); fma2(acc[1][4], a1, b4);
            fma2(acc[2][0], a2, b0); fma2(acc[2][1], a2, b1); fma2(acc[2][2], a2, b2);
            fma2(acc[2][3], a2, b3); fma2(acc[2][4], a2, b4);
            fma2(acc[3][0], a3, b0); fma2(acc[3][1], a3, b1); fma2(acc[3][2], a3, b2);
            fma2(acc[3][3], a3, b3); fma2(acc[3][4], a3, b4);
        }
        __syncthreads();
    }

    float* Y = g_Ypart[blockIdx.y];
#pragma unroll
    for (int r = 0; r < 4; r++)
#pragma unroll
        for (int p = 0; p < 5; p++)
            *(ull*)(Y + (size_t)(row0 + rg * 4 + r) * MCOLS + cg * 10 + 2 * p) = acc[r][p];
}

// ---------------------------------------------------------------------------
// Kernel 3: combine partials, denom, elu, write [N, 64]
// ---------------------------------------------------------------------------
__global__ void __launch_bounds__(256) finalize_kernel(float* __restrict__ out) {
    int tid = threadIdx.x;
    int t = tid & 63;
    int i = blockIdx.x * 4 + (tid >> 6);
    int h = t >> 3, u = t & 7;

    float y = 0.f, s = 0.f, deg = 0.f;
#pragma unroll
    for (int p = 0; p < KCH; p++) {
        const float* Yp = g_Ypart[p] + (size_t)i * MCOLS;
        y   += Yp[h * 9 + u];
        s   += Yp[h * 9 + 8];
        deg += Yp[72];
    }
    float eel = expf(g_EL[h * NN + i]);
    float denom = ((float)NN - deg) + eel * s;
    float v = eel * y / denom;
    out[i * 64 + t] = (v > 0.f) ? v : expm1f(v);
}

// ---------------------------------------------------------------------------
extern "C" void kernel_launch(void* const* d_in, const int* in_sizes, int n_in,
                              void* d_out, int out_size) {
    const float* A  = (const float*)d_in[0];
    const float* H  = (const float*)d_in[1];
    const float* W  = (const float*)d_in[2];
    const float* al = (const float*)d_in[3];
    const float* ar = (const float*)d_in[4];
    float* out = (float*)d_out;

    prep_kernel<<<128, 256>>>(H, W, al, ar);
    dim3 grid(NN / BM, KCH);
    spmm_kernel<<<grid, 256>>>(A);
    finalize_kernel<<<1024, 256>>>(out);
}

// round 9
// speedup vs baseline: 2.5925x; 1.9839x over previous
#include <cuda_runtime.h>
#include <cuda_bf16.h>
#include <math.h>
#include <stdint.h>

#define NN 4096
#define FF 128
#define OC 80            // Y cols (73 used: 8 heads x (8 V + exp_er) + deg)
#define KCH 4            // K-split of GEMM
#define GBM 64           // GEMM row tile per CTA
#define GBK 32           // GEMM k chunk (32 bf16 = 64B rows, SW64 swizzle)

// Scratch (__device__ globals; zero-initialized, rows 146..159 of g_Mt stay 0)
__device__ __nv_bfloat16 g_Mt[160 * NN];     // B op: row 2c = hi of col c, 2c+1 = lo
__device__ float g_EL[8 * NN];
__device__ float g_Ypart[KCH][NN * OC];

__device__ __forceinline__ uint32_t smem_u32(const void* p) {
    uint32_t a;
    asm("{ .reg .u64 t; cvta.to.shared.u64 t, %1; cvt.u32.u64 %0, t; }" : "=r"(a) : "l"(p));
    return a;
}
__device__ __forceinline__ void ldm4(uint32_t* r, uint32_t addr) {
    asm volatile("ldmatrix.sync.aligned.m8n8.x4.shared.b16 {%0,%1,%2,%3}, [%4];"
                 : "=r"(r[0]), "=r"(r[1]), "=r"(r[2]), "=r"(r[3]) : "r"(addr));
}
__device__ __forceinline__ void ldm2(uint32_t* r, uint32_t addr) {
    asm volatile("ldmatrix.sync.aligned.m8n8.x2.shared.b16 {%0,%1}, [%2];"
                 : "=r"(r[0]), "=r"(r[1]) : "r"(addr));
}
__device__ __forceinline__ void mma16816(float* c, const uint32_t* a, const uint32_t* b) {
    asm volatile("mma.sync.aligned.m16n8k16.row.col.f32.bf16.bf16.f32 "
                 "{%0,%1,%2,%3}, {%4,%5,%6,%7}, {%8,%9}, {%0,%1,%2,%3};"
                 : "+f"(c[0]), "+f"(c[1]), "+f"(c[2]), "+f"(c[3])
                 : "r"(a[0]), "r"(a[1]), "r"(a[2]), "r"(a[3]), "r"(b[0]), "r"(b[1]));
}

// ---------------------------------------------------------------------------
// Kernel 1: per node j compute V/e_l/e_r; emit transposed split-bf16 B matrix.
// 256 blocks x 256 threads, 16 nodes per block.
// ---------------------------------------------------------------------------
__global__ void __launch_bounds__(256) prep_kernel(const float* __restrict__ H,
                                                   const float* __restrict__ W,
                                                   const float* __restrict__ al,
                                                   const float* __restrict__ ar) {
    __shared__ __align__(16) float sW[FF * 64];   // 32 KB [f][hu]
    __shared__ __align__(16) float sH[16 * FF];   // 8 KB  [j][f]
    __shared__ float sC[72][16];

    int tid = threadIdx.x;
    int j0 = blockIdx.x * 16;

#pragma unroll
    for (int i = 0; i < 32; i++) {                // stage W scattered to [f][hu]
        int lin = tid + i * 256;                  // lin = h*1024 + f*8 + u
        int h = lin >> 10, f = (lin >> 3) & 127, u = lin & 7;
        sW[f * 64 + h * 8 + u] = W[lin];
    }
#pragma unroll
    for (int i = 0; i < 8; i++) {
        int lin = tid + i * 256;
        sH[lin] = H[(size_t)j0 * FF + lin];
    }
    __syncthreads();

    int hu = tid & 63, jj = tid >> 6;
    int h = hu >> 3, u = hu & 7;
    float alv = al[hu], arv = ar[hu];

#pragma unroll
    for (int jg = 0; jg < 4; jg++) {
        int jl = jj * 4 + jg;
        const float* hp = sH + jl * FF;
        float acc = 0.f;
#pragma unroll
        for (int f = 0; f < FF; f += 4) {
            float4 hv = *(const float4*)(hp + f);
            acc += hv.x * sW[(f + 0) * 64 + hu];
            acc += hv.y * sW[(f + 1) * 64 + hu];
            acc += hv.z * sW[(f + 2) * 64 + hu];
            acc += hv.w * sW[(f + 3) * 64 + hu];
        }
        float el = acc * alv, er = acc * arv;
#pragma unroll
        for (int m = 4; m; m >>= 1) {
            el += __shfl_xor_sync(0xffffffffu, el, m);
            er += __shfl_xor_sync(0xffffffffu, er, m);
        }
        float eer = expf(er);
        sC[h * 9 + u][jl] = eer * acc;            // V[h,j,u]
        if (u == 0) {
            sC[h * 9 + 8][jl] = eer;              // exp(e_r)
            g_EL[h * NN + j0 + jl] = el;
        }
    }
    __syncthreads();

    // 146 bf16 rows (hi/lo interleaved), coalesced-ish along j
    for (int idx = tid; idx < 146 * 16; idx += 256) {
        int r = idx >> 4, jl = idx & 15;
        int c = r >> 1;
        float v = (c == 72) ? 1.0f : sC[c][jl];
        __nv_bfloat16 hi = __float2bfloat16_rn(v);
        __nv_bfloat16 o = (r & 1) ? __float2bfloat16_rn(v - __bfloat162float(hi)) : hi;
        g_Mt[(size_t)r * NN + j0 + jl] = o;
    }
}

// ---------------------------------------------------------------------------
// Kernel 2: HMMA bf16 GEMM  Ypart[ks] = A_rows x Mt^T  (64 x 160 x 1024/CTA)
// mma.sync m16n8k16, ldmatrix fragments, SW64 smem, double-buffered.
// ---------------------------------------------------------------------------
__global__ void __launch_bounds__(256, 2) gemm_kernel(const float* __restrict__ A) {
    __shared__ __align__(128) __nv_bfloat16 sA[2][GBM * GBK];   // 2 x 4 KB
    __shared__ __align__(128) __nv_bfloat16 sB[2][160 * GBK];   // 2 x 10 KB

    int tid = threadIdx.x;
    int lane = tid & 31, wid = tid >> 5;
    int rg = wid >> 2, cg = wid & 3;              // warp grid 2 x 4

    const size_t arow0 = (size_t)(blockIdx.x * GBM) * NN + (size_t)blockIdx.y * (NN / KCH);
    const __nv_bfloat16* Bp = g_Mt + (size_t)blockIdx.y * (NN / KCH);

    uint32_t saA = smem_u32(sA);
    uint32_t saB = smem_u32(sB);

    // --- ldmatrix source address precompute (SW64: bits[5:4] ^= row bits[2:1]) ---
    uint32_t abase[2], akx[2];
#pragma unroll
    for (int mt = 0; mt < 2; mt++) {
        int row = rg * 32 + mt * 16 + (lane & 15);
        abase[mt] = row * 64;
        akx[mt] = ((row >> 1) & 3) << 4;
    }
    uint32_t khA = (lane >> 4) << 4;

    uint32_t bbase[3], bkx[3];
    {
        int n0 = cg * 40 + (lane & 7) + ((lane >> 4) << 3);
        int n1 = n0 + 16;
        int n2 = cg * 40 + 32 + (lane & 7);
        int ns[3] = {n0, n1, n2};
#pragma unroll
        for (int g = 0; g < 3; g++) {
            bbase[g] = ns[g] * 64;
            bkx[g] = ((ns[g] >> 1) & 3) << 4;
        }
    }
    uint32_t khB = ((lane >> 3) & 1) << 4;

    // --- staging store offsets ---
    uint32_t stA[2], stB[5];
#pragma unroll
    for (int t = 0; t < 2; t++) {
        int lin = tid + t * 256;
        int m = lin >> 3, kq = lin & 7;
        stA[t] = m * 64 + ((kq * 8) ^ (((m >> 1) & 3) << 4));
    }
#pragma unroll
    for (int t = 0; t < 5; t++) {
        int lin = tid + t * 256;
        int m = lin >> 3, kq = lin & 7;
        stB[t] = m * 64 + ((kq * 8) ^ (((m >> 1) & 3) << 4));
    }

    float acc[2][5][4];
#pragma unroll
    for (int mt = 0; mt < 2; mt++)
#pragma unroll
        for (int t = 0; t < 5; t++)
#pragma unroll
            for (int q = 0; q < 4; q++) acc[mt][t][q] = 0.f;

    float4 pa[2];
    uint2 pb[5];

#define LOAD_CHUNK(i)                                                          \
    {                                                                          \
        int kc = (i) * GBK;                                                    \
        _Pragma("unroll") for (int t = 0; t < 2; t++) {                        \
            int lin = tid + t * 256;                                           \
            int m = lin >> 3, kq = lin & 7;                                    \
            pa[t] = *(const float4*)(A + arow0 + (size_t)m * NN + kc + kq * 4);\
        }                                                                      \
        _Pragma("unroll") for (int t = 0; t < 5; t++) {                        \
            int lin = tid + t * 256;                                           \
            int m = lin >> 3, kq = lin & 7;                                    \
            pb[t] = *(const uint2*)(Bp + (size_t)m * NN + kc + kq * 4);        \
        }                                                                      \
    }

#define STORE_CHUNK(b)                                                         \
    {                                                                          \
        _Pragma("unroll") for (int t = 0; t < 2; t++) {                        \
            __nv_bfloat162 p0 = __floats2bfloat162_rn(pa[t].x, pa[t].y);       \
            __nv_bfloat162 p1 = __floats2bfloat162_rn(pa[t].z, pa[t].w);       \
            uint2 w;                                                           \
            w.x = *(uint32_t*)&p0;                                             \
            w.y = *(uint32_t*)&p1;                                             \
            *(uint2*)((char*)sA[b] + stA[t]) = w;                              \
        }                                                                      \
        _Pragma("unroll") for (int t = 0; t < 5; t++)                          \
            *(uint2*)((char*)sB[b] + stB[t]) = pb[t];                          \
    }

    LOAD_CHUNK(0);
    STORE_CHUNK(0);
    __syncthreads();

    for (int i = 0; i < 32; i++) {
        int b = i & 1;
        if (i < 31) LOAD_CHUNK(i + 1);

        uint32_t bufA = saA + b * (GBM * GBK * 2);
        uint32_t bufB = saB + b * (160 * GBK * 2);
#pragma unroll
        for (int ks = 0; ks < 2; ks++) {
            uint32_t kk = ks << 5;
            uint32_t a[2][4];
            ldm4(a[0], bufA + abase[0] + ((kk | khA) ^ akx[0]));
            ldm4(a[1], bufA + abase[1] + ((kk | khA) ^ akx[1]));
            uint32_t bb[5][2];
            {
                uint32_t t01[4], t23[4];
                ldm4(t01, bufB + bbase[0] + ((kk | khB) ^ bkx[0]));
                ldm4(t23, bufB + bbase[1] + ((kk | khB) ^ bkx[1]));
                bb[0][0] = t01[0]; bb[0][1] = t01[1];
                bb[1][0] = t01[2]; bb[1][1] = t01[3];
                bb[2][0] = t23[0]; bb[2][1] = t23[1];
                bb[3][0] = t23[2]; bb[3][1] = t23[3];
                ldm2(bb[4], bufB + bbase[2] + ((kk | khB) ^ bkx[2]));
            }
#pragma unroll
            for (int mt = 0; mt < 2; mt++)
#pragma unroll
                for (int t = 0; t < 5; t++)
                    mma16816(acc[mt][t], a[mt], bb[t]);
        }

        if (i < 31) {
            __syncthreads();
            STORE_CHUNK(1 - b);
            __syncthreads();
        }
    }

    // Epilogue: pair-sum hi/lo (c0+c1, c2+c3 are exactly the hi/lo D columns)
    float* Yp = g_Ypart[blockIdx.y];
    int rbase = blockIdx.x * GBM + rg * 32 + (lane >> 2);
    int cbase = cg * 20 + (lane & 3);
#pragma unroll
    for (int mt = 0; mt < 2; mt++)
#pragma unroll
        for (int t = 0; t < 5; t++) {
            int r = rbase + mt * 16;
            int c = cbase + t * 4;
            Yp[(size_t)r * OC + c]       = acc[mt][t][0] + acc[mt][t][1];
            Yp[(size_t)(r + 8) * OC + c] = acc[mt][t][2] + acc[mt][t][3];
        }
}

// ---------------------------------------------------------------------------
// Kernel 3: combine K-split partials, denom, elu, write [N, 64]
// ---------------------------------------------------------------------------
__global__ void __launch_bounds__(256) finalize_kernel(float* __restrict__ out) {
    int tid = threadIdx.x;
    int t = tid & 63;
    int i = blockIdx.x * 4 + (tid >> 6);
    int h = t >> 3, u = t & 7;

    float y = 0.f, s = 0.f, deg = 0.f;
#pragma unroll
    for (int p = 0; p < KCH; p++) {
        const float* Yp = g_Ypart[p] + (size_t)i * OC;
        y   += Yp[h * 9 + u];
        s   += Yp[h * 9 + 8];
        deg += Yp[72];
    }
    float eel = expf(g_EL[h * NN + i]);
    float denom = ((float)NN - deg) + eel * s;
    float v = eel * y / denom;
    out[i * 64 + t] = (v > 0.f) ? v : expm1f(v);
}

// ---------------------------------------------------------------------------
extern "C" void kernel_launch(void* const* d_in, const int* in_sizes, int n_in,
                              void* d_out, int out_size) {
    const float* A  = (const float*)d_in[0];
    const float* H  = (const float*)d_in[1];
    const float* W  = (const float*)d_in[2];
    const float* al = (const float*)d_in[3];
    const float* ar = (const float*)d_in[4];
    float* out = (float*)d_out;

    prep_kernel<<<256, 256>>>(H, W, al, ar);
    dim3 grid(NN / GBM, KCH);
    gemm_kernel<<<grid, 256>>>(A);
    finalize_kernel<<<1024, 256>>>(out);
}

// round 10
// speedup vs baseline: 2.7906x; 1.0764x over previous
#include <cuda_runtime.h>
#include <cuda_bf16.h>
#include <math.h>
#include <stdint.h>

#define NN 4096
#define FF 128
#define OC 80            // Y cols (73 used: 8 heads x (8 V + exp_er) + deg)
#define KCH 4            // K-split of GEMM
#define GBM 128          // GEMM row tile per CTA
#define GBK 32           // GEMM k chunk (32 bf16 = 64B rows, SW64 swizzle)

// Scratch (__device__ globals; zero-initialized, rows 146..159 of g_Mt stay 0)
__device__ __nv_bfloat16 g_Mt[160 * NN];     // B op: row 2c = hi of col c, 2c+1 = lo
__device__ float g_EL[8 * NN];
__device__ float g_Ypart[KCH][NN * OC];

__device__ __forceinline__ uint32_t smem_u32(const void* p) {
    uint32_t a;
    asm("{ .reg .u64 t; cvta.to.shared.u64 t, %1; cvt.u32.u64 %0, t; }" : "=r"(a) : "l"(p));
    return a;
}
__device__ __forceinline__ void ldm4(uint32_t* r, uint32_t addr) {
    asm volatile("ldmatrix.sync.aligned.m8n8.x4.shared.b16 {%0,%1,%2,%3}, [%4];"
                 : "=r"(r[0]), "=r"(r[1]), "=r"(r[2]), "=r"(r[3]) : "r"(addr));
}
__device__ __forceinline__ void mma16816(float* c, const uint32_t* a, const uint32_t* b) {
    asm volatile("mma.sync.aligned.m16n8k16.row.col.f32.bf16.bf16.f32 "
                 "{%0,%1,%2,%3}, {%4,%5,%6,%7}, {%8,%9}, {%0,%1,%2,%3};"
                 : "+f"(c[0]), "+f"(c[1]), "+f"(c[2]), "+f"(c[3])
                 : "r"(a[0]), "r"(a[1]), "r"(a[2]), "r"(a[3]), "r"(b[0]), "r"(b[1]));
}

// ---------------------------------------------------------------------------
// Kernel 1: per node j compute V/e_l/e_r; emit transposed split-bf16 B matrix.
// 256 blocks x 256 threads, 16 nodes per block. Thread = (hu, jj) accumulates
// 4 nodes at once; sW transposed [hu][f] (pad 132) -> all lds.128, no conflicts.
// ---------------------------------------------------------------------------
__global__ void __launch_bounds__(256) prep_kernel(const float* __restrict__ H,
                                                   const float* __restrict__ W,
                                                   const float* __restrict__ al,
                                                   const float* __restrict__ ar) {
    __shared__ __align__(16) float sW[64 * 132];  // [hu][f], padded
    __shared__ __align__(16) float sH[16 * FF];   // [j][f]
    __shared__ float sC[72][16];

    int tid = threadIdx.x;
    int j0 = blockIdx.x * 16;

#pragma unroll 4
    for (int i = 0; i < 32; i++) {                // stage W -> sW[(h*8+u)][f]
        int lin = tid + i * 256;                  // lin = h*1024 + f*8 + u
        int h = lin >> 10, f = (lin >> 3) & 127, u = lin & 7;
        sW[(h * 8 + u) * 132 + f] = W[lin];
    }
#pragma unroll
    for (int i = 0; i < 8; i++) {
        int lin = tid + i * 256;
        sH[lin] = H[(size_t)j0 * FF + lin];
    }
    __syncthreads();

    int hu = tid & 63, jj = tid >> 6;
    int h = hu >> 3, u = hu & 7;

    float acc[4] = {0.f, 0.f, 0.f, 0.f};
    const float* wp = sW + hu * 132;
    const float* hp = sH + jj * 4 * FF;
#pragma unroll 8
    for (int f = 0; f < FF; f += 4) {
        float4 wv = *(const float4*)(wp + f);
#pragma unroll
        for (int jg = 0; jg < 4; jg++) {
            float4 hv = *(const float4*)(hp + jg * FF + f);
            acc[jg] += hv.x * wv.x + hv.y * wv.y + hv.z * wv.z + hv.w * wv.w;
        }
    }

    float alv = al[hu], arv = ar[hu];
#pragma unroll
    for (int jg = 0; jg < 4; jg++) {
        int jl = jj * 4 + jg;
        float el = acc[jg] * alv, er = acc[jg] * arv;
#pragma unroll
        for (int m = 4; m; m >>= 1) {
            el += __shfl_xor_sync(0xffffffffu, el, m);
            er += __shfl_xor_sync(0xffffffffu, er, m);
        }
        float eer = expf(er);
        sC[h * 9 + u][jl] = eer * acc[jg];        // V[h,j,u]
        if (u == 0) {
            sC[h * 9 + 8][jl] = eer;              // exp(e_r)
            g_EL[h * NN + j0 + jl] = el;
        }
    }
    __syncthreads();

    // 146 bf16 rows (hi/lo interleaved), along j
    for (int idx = tid; idx < 146 * 16; idx += 256) {
        int r = idx >> 4, jl = idx & 15;
        int c = r >> 1;
        float v = (c == 72) ? 1.0f : sC[c][jl];
        __nv_bfloat16 hi = __float2bfloat16_rn(v);
        __nv_bfloat16 o = (r & 1) ? __float2bfloat16_rn(v - __bfloat162float(hi)) : hi;
        g_Mt[(size_t)r * NN + j0 + jl] = o;
    }
}

// ---------------------------------------------------------------------------
// Kernel 2: HMMA bf16 GEMM  Ypart[ks] = A_rows x Mt^T  (128 x 160 x 1024/CTA)
// grid (32, 4) = 128 CTAs = one wave. Warp grid 4x2: 32 rows x 80 cols/warp.
// ---------------------------------------------------------------------------
__global__ void __launch_bounds__(256) gemm_kernel(const float* __restrict__ A) {
    __shared__ __align__(128) __nv_bfloat16 sA[2][GBM * GBK];   // 2 x 8 KB
    __shared__ __align__(128) __nv_bfloat16 sB[2][160 * GBK];   // 2 x 10 KB

    int tid = threadIdx.x;
    int lane = tid & 31, wid = tid >> 5;
    int rg = wid & 3, cg = wid >> 2;              // warp grid 4 x 2

    const size_t arow0 = (size_t)(blockIdx.x * GBM) * NN + (size_t)blockIdx.y * (NN / KCH);
    const __nv_bfloat16* Bp = g_Mt + (size_t)blockIdx.y * (NN / KCH);

    uint32_t saA = smem_u32(sA);
    uint32_t saB = smem_u32(sB);

    // ldmatrix source addresses (SW64: bits[5:4] ^= row bits[2:1])
    uint32_t abase[2], akx[2];
#pragma unroll
    for (int mt = 0; mt < 2; mt++) {
        int row = rg * 32 + mt * 16 + (lane & 15);
        abase[mt] = row * 64;
        akx[mt] = ((row >> 1) & 3) << 4;
    }
    uint32_t khA = (lane >> 4) << 4;

    uint32_t bbase[5], bkx[5];
#pragma unroll
    for (int g = 0; g < 5; g++) {
        int n = cg * 80 + g * 16 + (lane & 7) + ((lane >> 4) << 3);
        bbase[g] = n * 64;
        bkx[g] = ((n >> 1) & 3) << 4;
    }
    uint32_t khB = ((lane >> 3) & 1) << 4;

    // staging store offsets
    uint32_t stA[4], stB[5];
#pragma unroll
    for (int t = 0; t < 4; t++) {
        int lin = tid + t * 256;
        int m = lin >> 3, kq = lin & 7;
        stA[t] = m * 64 + ((kq * 8) ^ (((m >> 1) & 3) << 4));
    }
#pragma unroll
    for (int t = 0; t < 5; t++) {
        int lin = tid + t * 256;
        int m = lin >> 3, kq = lin & 7;
        stB[t] = m * 64 + ((kq * 8) ^ (((m >> 1) & 3) << 4));
    }

    float acc[2][10][4];
#pragma unroll
    for (int mt = 0; mt < 2; mt++)
#pragma unroll
        for (int t = 0; t < 10; t++)
#pragma unroll
            for (int q = 0; q < 4; q++) acc[mt][t][q] = 0.f;

    float4 pa[4];
    uint2 pb[5];

#define LOAD_CHUNK(i)                                                          \
    {                                                                          \
        int kc = (i) * GBK;                                                    \
        _Pragma("unroll") for (int t = 0; t < 4; t++) {                        \
            int lin = tid + t * 256;                                           \
            int m = lin >> 3, kq = lin & 7;                                    \
            pa[t] = *(const float4*)(A + arow0 + (size_t)m * NN + kc + kq * 4);\
        }                                                                      \
        _Pragma("unroll") for (int t = 0; t < 5; t++) {                        \
            int lin = tid + t * 256;                                           \
            int m = lin >> 3, kq = lin & 7;                                    \
            pb[t] = *(const uint2*)(Bp + (size_t)m * NN + kc + kq * 4);        \
        }                                                                      \
    }

#define STORE_CHUNK(b)                                                         \
    {                                                                          \
        _Pragma("unroll") for (int t = 0; t < 4; t++) {                        \
            __nv_bfloat162 p0 = __floats2bfloat162_rn(pa[t].x, pa[t].y);       \
            __nv_bfloat162 p1 = __floats2bfloat162_rn(pa[t].z, pa[t].w);       \
            uint2 w;                                                           \
            w.x = *(uint32_t*)&p0;                                             \
            w.y = *(uint32_t*)&p1;                                             \
            *(uint2*)((char*)sA[b] + stA[t]) = w;                              \
        }                                                                      \
        _Pragma("unroll") for (int t = 0; t < 5; t++)                          \
            *(uint2*)((char*)sB[b] + stB[t]) = pb[t];                          \
    }

    LOAD_CHUNK(0);
    STORE_CHUNK(0);
    __syncthreads();

    for (int i = 0; i < 32; i++) {
        int b = i & 1;
        if (i < 31) LOAD_CHUNK(i + 1);

        uint32_t bufA = saA + b * (GBM * GBK * 2);
        uint32_t bufB = saB + b * (160 * GBK * 2);
#pragma unroll
        for (int ks = 0; ks < 2; ks++) {
            uint32_t kk = ks << 5;
            uint32_t a[2][4];
            ldm4(a[0], bufA + abase[0] + ((kk | khA) ^ akx[0]));
            ldm4(a[1], bufA + abase[1] + ((kk | khA) ^ akx[1]));
            uint32_t bb[10][2];
#pragma unroll
            for (int g = 0; g < 5; g++) {
                uint32_t tr[4];
                ldm4(tr, bufB + bbase[g] + ((kk | khB) ^ bkx[g]));
                bb[2 * g][0] = tr[0]; bb[2 * g][1] = tr[1];
                bb[2 * g + 1][0] = tr[2]; bb[2 * g + 1][1] = tr[3];
            }
#pragma unroll
            for (int mt = 0; mt < 2; mt++)
#pragma unroll
                for (int t = 0; t < 10; t++)
                    mma16816(acc[mt][t], a[mt], bb[t]);
        }

        if (i < 31) {
            __syncthreads();
            STORE_CHUNK(1 - b);
            __syncthreads();
        }
    }

    // Epilogue: pair-sum hi/lo D columns
    float* Yp = g_Ypart[blockIdx.y];
    int rbase = blockIdx.x * GBM + rg * 32 + (lane >> 2);
    int cbase = cg * 40 + (lane & 3);
#pragma unroll
    for (int mt = 0; mt < 2; mt++)
#pragma unroll
        for (int t = 0; t < 10; t++) {
            int r = rbase + mt * 16;
            int c = cbase + t * 4;
            Yp[(size_t)r * OC + c]       = acc[mt][t][0] + acc[mt][t][1];
            Yp[(size_t)(r + 8) * OC + c] = acc[mt][t][2] + acc[mt][t][3];
        }
}

// ---------------------------------------------------------------------------
// Kernel 3: combine K-split partials, denom, elu, write [N, 64]
// ---------------------------------------------------------------------------
__global__ void __launch_bounds__(256) finalize_kernel(float* __restrict__ out) {
    int tid = threadIdx.x;
    int t = tid & 63;
    int i = blockIdx.x * 4 + (tid >> 6);
    int h = t >> 3, u = t & 7;

    float y = 0.f, s = 0.f, deg = 0.f;
#pragma unroll
    for (int p = 0; p < KCH; p++) {
        const float* Yp = g_Ypart[p] + (size_t)i * OC;
        y   += Yp[h * 9 + u];
        s   += Yp[h * 9 + 8];
        deg += Yp[72];
    }
    float eel = expf(g_EL[h * NN + i]);
    float denom = ((float)NN - deg) + eel * s;
    float v = eel * y / denom;
    out[i * 64 + t] = (v > 0.f) ? v : expm1f(v);
}

// ---------------------------------------------------------------------------
extern "C" void kernel_launch(void* const* d_in, const int* in_sizes, int n_in,
                              void* d_out, int out_size) {
    const float* A  = (const float*)d_in[0];
    const float* H  = (const float*)d_in[1];
    const float* W  = (const float*)d_in[2];
    const float* al = (const float*)d_in[3];
    const float* ar = (const float*)d_in[4];
    float* out = (float*)d_out;

    prep_kernel<<<256, 256>>>(H, W, al, ar);
    dim3 grid(NN / GBM, KCH);
    gemm_kernel<<<grid, 256>>>(A);
    finalize_kernel<<<1024, 256>>>(out);
}